// round 4
// baseline (speedup 1.0000x reference)
#include <cuda_runtime.h>
#include <math.h>

#define MAXB 16384

// ---------------- device scratch (no allocations allowed) ----------------
__device__ float g_WhhEt[64 * 256];   // W_hh_e transposed: [k][gate]
__device__ float g_WhhDt[64 * 256];   // W_hh_d transposed: [k][gate]
__device__ float g_WxEt[4 * 256];     // folded enc input weights: [j][gate]
__device__ float g_WxDt[4 * 256];     // folded dec input weights: [j][gate]
__device__ float g_bxE[256];          // folded enc bias
__device__ float g_bxD[256];          // folded dec bias
__device__ float g_hTt[64 * MAXB];    // encoder final h, transposed [k][row]
__device__ float g_dhT[64 * MAXB];    // decoder init h/c, transposed [k][row]
__device__ float g_epsT[100 * MAXB];  // eps transposed [l][row]

__device__ __forceinline__ float sigf(float x) { return 1.0f / (1.0f + expf(-x)); }
__device__ __forceinline__ float leakyf(float x) { return x >= 0.0f ? x : 0.01f * x; }
__device__ __forceinline__ void fma4(float4& a, const float4 h, float w) {
    a.x = fmaf(h.x, w, a.x);
    a.y = fmaf(h.y, w, a.y);
    a.z = fmaf(h.z, w, a.z);
    a.w = fmaf(h.w, w, a.w);
}

// ---------------- prep: fold embedding into input projection + transposes ----------------
__global__ void k_fold(const float* __restrict__ W_se, const float* __restrict__ b_se,
                       const float* __restrict__ W_ih_e, const float* __restrict__ W_hh_e,
                       const float* __restrict__ b_ih_e, const float* __restrict__ b_hh_e,
                       const float* __restrict__ W_ih_d, const float* __restrict__ W_hh_d,
                       const float* __restrict__ b_ih_d, const float* __restrict__ b_hh_d) {
    int g = threadIdx.x;  // 256 threads, one gate each
    // encoder fold: Wx[g][j] = sum_e W_ih_e[g][e] * W_se[e][j];  bx[g] = W_ih_e[g]·b_se + b_ih + b_hh
    {
        float wj0 = 0.f, wj1 = 0.f, wj2 = 0.f, wj3 = 0.f, bb = 0.f;
        for (int e = 0; e < 64; e++) {
            float wie = W_ih_e[g * 64 + e];
            bb = fmaf(wie, b_se[e], bb);
            wj0 = fmaf(wie, W_se[e * 4 + 0], wj0);
            wj1 = fmaf(wie, W_se[e * 4 + 1], wj1);
            wj2 = fmaf(wie, W_se[e * 4 + 2], wj2);
            wj3 = fmaf(wie, W_se[e * 4 + 3], wj3);
        }
        g_WxEt[0 * 256 + g] = wj0;
        g_WxEt[1 * 256 + g] = wj1;
        g_WxEt[2 * 256 + g] = wj2;
        g_WxEt[3 * 256 + g] = wj3;
        g_bxE[g] = bb + b_ih_e[g] + b_hh_e[g];
    }
    // decoder fold
    {
        float wj0 = 0.f, wj1 = 0.f, wj2 = 0.f, wj3 = 0.f, bb = 0.f;
        for (int e = 0; e < 64; e++) {
            float wid = W_ih_d[g * 64 + e];
            bb = fmaf(wid, b_se[e], bb);
            wj0 = fmaf(wid, W_se[e * 4 + 0], wj0);
            wj1 = fmaf(wid, W_se[e * 4 + 1], wj1);
            wj2 = fmaf(wid, W_se[e * 4 + 2], wj2);
            wj3 = fmaf(wid, W_se[e * 4 + 3], wj3);
        }
        g_WxDt[0 * 256 + g] = wj0;
        g_WxDt[1 * 256 + g] = wj1;
        g_WxDt[2 * 256 + g] = wj2;
        g_WxDt[3 * 256 + g] = wj3;
        g_bxD[g] = bb + b_ih_d[g] + b_hh_d[g];
    }
    // transpose recurrent weights to [k][gate]
    for (int idx = g; idx < 64 * 256; idx += 256) {
        int k = idx >> 8, gg = idx & 255;
        g_WhhEt[idx] = W_hh_e[gg * 64 + k];
        g_WhhDt[idx] = W_hh_d[gg * 64 + k];
    }
}

// ---------------- transpose eps for coalesced access ----------------
__global__ void k_epsT(const float* __restrict__ eps, int B) {
    int i = blockIdx.x * blockDim.x + threadIdx.x;
    int n = 100 * B;
    if (i < n) {
        int l = i / B;
        int r = i - l * B;
        g_epsT[i] = eps[(size_t)r * 100 + l];
    }
}

// ---------------- copy expert_traj to output slot ----------------
__global__ void k_copy(const float4* __restrict__ src, float4* __restrict__ dst, int n4) {
    int i = blockIdx.x * blockDim.x + threadIdx.x;
    if (i < n4) dst[i] = src[i];
}

// ---------------- encoder LSTM ----------------
// 64 rows/block, 256 threads. thread = (rg = rows rg*4..+3, hg = h-indices hg*4..+3).
__global__ __launch_bounds__(256, 2) void k_enc(const float* __restrict__ traj, int B) {
    extern __shared__ float sm[];
    float* sWt = sm;                 // 16384: W_hh_e^T [k][gate]
    float* sWx = sm + 16384;         // 1024:  folded x weights [j][gate]
    float* sbx = sWx + 1024;         // 256:   folded bias
    float* h_sm = sbx + 256;         // 4096:  h state [k][row]
    float* inp_sm = h_sm + 4096;     // 256:   staged inp [j][row]
    const int tid = threadIdx.x;
    const int base = blockIdx.x * 64;
    const int rg = tid & 15;
    const int hg = tid >> 4;

    for (int i = tid; i < 16384; i += 256) sWt[i] = g_WhhEt[i];
    for (int i = tid; i < 1024; i += 256) sWx[i] = g_WxEt[i];
    sbx[tid] = g_bxE[tid];
    for (int i = tid; i < 4096; i += 256) h_sm[i] = 0.0f;

    float4 creg[4];
#pragma unroll
    for (int hi = 0; hi < 4; hi++) creg[hi] = make_float4(0.f, 0.f, 0.f, 0.f);
    float4 prevtr = make_float4(0.f, 0.f, 0.f, 0.f);  // rel[0] = traj[0] - 0
    const float* trow = traj + (size_t)(base + (tid & 63)) * 120;
    __syncthreads();

    for (int t = 0; t < 30; t++) {
        if (tid < 64) {
            float4 tr = *(const float4*)(trow + t * 4);
            inp_sm[tid] = tr.x - prevtr.x;
            inp_sm[64 + tid] = tr.y - prevtr.y;
            inp_sm[128 + tid] = tr.z;
            inp_sm[192 + tid] = tr.w;
            prevtr = tr;
        }
        __syncthreads();

        float4 acc[4][4];  // [gate chunk i,f,g,o][h-index], float4 over 4 rows
#pragma unroll
        for (int ch = 0; ch < 4; ch++) {
            float4 bv = *(const float4*)&sbx[ch * 64 + hg * 4];
            acc[ch][0] = make_float4(bv.x, bv.x, bv.x, bv.x);
            acc[ch][1] = make_float4(bv.y, bv.y, bv.y, bv.y);
            acc[ch][2] = make_float4(bv.z, bv.z, bv.z, bv.z);
            acc[ch][3] = make_float4(bv.w, bv.w, bv.w, bv.w);
        }
#pragma unroll
        for (int j = 0; j < 4; j++) {
            float4 xv = *(const float4*)&inp_sm[j * 64 + rg * 4];
#pragma unroll
            for (int ch = 0; ch < 4; ch++) {
                float4 wv = *(const float4*)&sWx[j * 256 + ch * 64 + hg * 4];
                fma4(acc[ch][0], xv, wv.x);
                fma4(acc[ch][1], xv, wv.y);
                fma4(acc[ch][2], xv, wv.z);
                fma4(acc[ch][3], xv, wv.w);
            }
        }
#pragma unroll 4
        for (int k = 0; k < 64; k++) {
            float4 hv = *(const float4*)&h_sm[k * 64 + rg * 4];
#pragma unroll
            for (int ch = 0; ch < 4; ch++) {
                float4 wv = *(const float4*)&sWt[k * 256 + ch * 64 + hg * 4];
                fma4(acc[ch][0], hv, wv.x);
                fma4(acc[ch][1], hv, wv.y);
                fma4(acc[ch][2], hv, wv.z);
                fma4(acc[ch][3], hv, wv.w);
            }
        }
        __syncthreads();  // all h_sm reads done before overwrite
#pragma unroll
        for (int hi = 0; hi < 4; hi++) {
            float4 iv = acc[0][hi], fv = acc[1][hi], gv = acc[2][hi], ov = acc[3][hi];
            float4 c = creg[hi];
            float4 hn;
            c.x = sigf(fv.x) * c.x + sigf(iv.x) * tanhf(gv.x); hn.x = sigf(ov.x) * tanhf(c.x);
            c.y = sigf(fv.y) * c.y + sigf(iv.y) * tanhf(gv.y); hn.y = sigf(ov.y) * tanhf(c.y);
            c.z = sigf(fv.z) * c.z + sigf(iv.z) * tanhf(gv.z); hn.z = sigf(ov.z) * tanhf(c.z);
            c.w = sigf(fv.w) * c.w + sigf(iv.w) * tanhf(gv.w); hn.w = sigf(ov.w) * tanhf(c.w);
            creg[hi] = c;
            *(float4*)&h_sm[(hg * 4 + hi) * 64 + rg * 4] = hn;
            if (t == 29)
                *(float4*)&g_hTt[(size_t)(hg * 4 + hi) * B + base + rg * 4] = hn;
        }
    }
}

// ---------------- MLPs + reparameterize + decoder-init projection ----------------
__global__ __launch_bounds__(256) void k_mlp(
    const float* __restrict__ mean_Ws, const float* __restrict__ mean_bs,
    const float* __restrict__ mean_Wf, const float* __restrict__ mean_bf,
    const float* __restrict__ lv_Ws, const float* __restrict__ lv_bs,
    const float* __restrict__ lv_Wf, const float* __restrict__ lv_bf,
    const float* __restrict__ W_init, const float* __restrict__ b_init,
    float* __restrict__ mu_out, float* __restrict__ lv_out, int B) {
    extern __shared__ float sm[];
    float* hin = sm;             // 4096  original hT [in][row]
    float* ha = sm + 4096;       // 4096
    float* hb = sm + 8192;       // 4096
    float* wbuf = sm + 12288;    // 6400  transposed layer weights
    float* sb = sm + 18688;      // 128   bias
    float* mubuf = sm + 18816;   // 6400  [out][row]
    float* lvbuf = sm + 25216;   // 6400  [out][row], becomes z
    const int tid = threadIdx.x;
    const int base = blockIdx.x * 64;
    const int rg = tid & 15;
    const int og = tid >> 4;

    for (int idx = tid; idx < 4096; idx += 256) {
        int k = idx >> 6, r = idx & 63;
        hin[idx] = g_hTt[(size_t)k * B + base + r];
    }

    for (int path = 0; path < 2; path++) {
        const float* Ws = path ? lv_Ws : mean_Ws;
        const float* bs = path ? lv_bs : mean_bs;
        const float* Wf = path ? lv_Wf : mean_Wf;
        const float* bf = path ? lv_bf : mean_bf;
        float* obuf = path ? lvbuf : mubuf;
        float* gout = path ? lv_out : mu_out;
        float* src = hin;
        float* dst = ha;
        for (int l = 0; l < 3; l++) {
            __syncthreads();
            for (int idx = tid; idx < 4096; idx += 256) {
                int out = idx >> 6, in = idx & 63;
                wbuf[in * 64 + out] = Ws[l * 4096 + idx];
            }
            if (tid < 64) sb[tid] = bs[l * 64 + tid];
            __syncthreads();
            float4 acc[4];
#pragma unroll
            for (int oi = 0; oi < 4; oi++) {
                float b = sb[og * 4 + oi];
                acc[oi] = make_float4(b, b, b, b);
            }
#pragma unroll 4
            for (int in = 0; in < 64; in++) {
                float4 hv = *(const float4*)&src[in * 64 + rg * 4];
                float4 wv = *(const float4*)&wbuf[in * 64 + og * 4];
                fma4(acc[0], hv, wv.x);
                fma4(acc[1], hv, wv.y);
                fma4(acc[2], hv, wv.z);
                fma4(acc[3], hv, wv.w);
            }
#pragma unroll
            for (int oi = 0; oi < 4; oi++) {
                float4 v = acc[oi];
                v.x = leakyf(v.x); v.y = leakyf(v.y); v.z = leakyf(v.z); v.w = leakyf(v.w);
                *(float4*)&dst[(og * 4 + oi) * 64 + rg * 4] = v;
            }
            src = dst;
            dst = (dst == ha) ? hb : ha;
        }
        // final layer: 64 -> 100, leaky
        __syncthreads();
        for (int idx = tid; idx < 6400; idx += 256) {
            int out = idx >> 6, in = idx & 63;
            wbuf[in * 100 + out] = Wf[idx];
        }
        if (tid < 100) sb[tid] = bf[tid];
        __syncthreads();
        for (int c = og; c < 25; c += 16) {
            float4 acc[4];
#pragma unroll
            for (int oi = 0; oi < 4; oi++) {
                float b = sb[c * 4 + oi];
                acc[oi] = make_float4(b, b, b, b);
            }
#pragma unroll 4
            for (int in = 0; in < 64; in++) {
                float4 hv = *(const float4*)&src[in * 64 + rg * 4];
                float4 wv = *(const float4*)&wbuf[in * 100 + c * 4];
                fma4(acc[0], hv, wv.x);
                fma4(acc[1], hv, wv.y);
                fma4(acc[2], hv, wv.z);
                fma4(acc[3], hv, wv.w);
            }
#pragma unroll
            for (int oi = 0; oi < 4; oi++) {
                acc[oi].x = leakyf(acc[oi].x);
                acc[oi].y = leakyf(acc[oi].y);
                acc[oi].z = leakyf(acc[oi].z);
                acc[oi].w = leakyf(acc[oi].w);
                *(float4*)&obuf[(c * 4 + oi) * 64 + rg * 4] = acc[oi];
            }
            float4 r0 = make_float4(acc[0].x, acc[1].x, acc[2].x, acc[3].x);
            float4 r1 = make_float4(acc[0].y, acc[1].y, acc[2].y, acc[3].y);
            float4 r2 = make_float4(acc[0].z, acc[1].z, acc[2].z, acc[3].z);
            float4 r3 = make_float4(acc[0].w, acc[1].w, acc[2].w, acc[3].w);
            *(float4*)&gout[(size_t)(base + rg * 4 + 0) * 100 + c * 4] = r0;
            *(float4*)&gout[(size_t)(base + rg * 4 + 1) * 100 + c * 4] = r1;
            *(float4*)&gout[(size_t)(base + rg * 4 + 2) * 100 + c * 4] = r2;
            *(float4*)&gout[(size_t)(base + rg * 4 + 3) * 100 + c * 4] = r3;
        }
    }
    // z = tanh(eps * exp(0.5*lv) + mu), in place in lvbuf
    __syncthreads();
    for (int idx = tid; idx < 6400; idx += 256) {
        int l = idx >> 6, r = idx & 63;
        float e = g_epsT[(size_t)l * B + base + r];
        lvbuf[idx] = tanhf(fmaf(e, expf(0.5f * lvbuf[idx]), mubuf[idx]));
    }
    __syncthreads();
    // dh = z @ W_init^T + b_init, store transposed
    for (int idx = tid; idx < 6400; idx += 256) {
        int k = idx / 100, l = idx - k * 100;
        wbuf[l * 64 + k] = W_init[idx];
    }
    if (tid < 64) sb[tid] = b_init[tid];
    __syncthreads();
    {
        float4 acc[4];
#pragma unroll
        for (int oi = 0; oi < 4; oi++) {
            float b = sb[og * 4 + oi];
            acc[oi] = make_float4(b, b, b, b);
        }
#pragma unroll 4
        for (int l = 0; l < 100; l++) {
            float4 zv = *(const float4*)&lvbuf[l * 64 + rg * 4];
            float4 wv = *(const float4*)&wbuf[l * 64 + og * 4];
            fma4(acc[0], zv, wv.x);
            fma4(acc[1], zv, wv.y);
            fma4(acc[2], zv, wv.z);
            fma4(acc[3], zv, wv.w);
        }
#pragma unroll
        for (int oi = 0; oi < 4; oi++)
            *(float4*)&g_dhT[(size_t)(og * 4 + oi) * B + base + rg * 4] = acc[oi];
    }
}

// ---------------- decoder LSTM + controls + dynamics ----------------
__global__ __launch_bounds__(256, 2) void k_dec(const float* __restrict__ init_state,
                                                const float* __restrict__ W_c,
                                                const float* __restrict__ b_c,
                                                float* __restrict__ recons, int B) {
    extern __shared__ float sm[];
    float* sWt = sm;               // 16384
    float* sWx = sm + 16384;       // 1024
    float* sbx = sWx + 1024;       // 256
    float* h_sm = sbx + 256;       // 4096
    float* inp_sm = h_sm + 4096;   // 256
    float* sWc = inp_sm + 256;     // 128
    float* sbc = sWc + 128;        // 4
    const int tid = threadIdx.x;
    const int base = blockIdx.x * 64;
    const int rg = tid & 15;
    const int hg = tid >> 4;

    for (int i = tid; i < 16384; i += 256) sWt[i] = g_WhhDt[i];
    for (int i = tid; i < 1024; i += 256) sWx[i] = g_WxDt[i];
    sbx[tid] = g_bxD[tid];
    if (tid < 128) sWc[tid] = W_c[tid];
    if (tid < 2) sbc[tid] = b_c[tid];
    for (int idx = tid; idx < 4096; idx += 256) {
        int k = idx >> 6, r = idx & 63;
        h_sm[idx] = g_dhT[(size_t)k * B + base + r];
    }
    float4 creg[4];
#pragma unroll
    for (int hi = 0; hi < 4; hi++)
        creg[hi] = *(const float4*)&g_dhT[(size_t)(hg * 4 + hi) * B + base + rg * 4];
    float4 prev = make_float4(0.f, 0.f, 0.f, 0.f);
    if (tid < 64) prev = *(const float4*)&init_state[(size_t)(base + tid) * 4];
    __syncthreads();

    for (int t = 0; t < 30; t++) {
        if (tid < 64) {
            inp_sm[tid] = prev.x;
            inp_sm[64 + tid] = prev.y;
            inp_sm[128 + tid] = prev.z;
            inp_sm[192 + tid] = prev.w;
        }
        __syncthreads();

        float4 acc[4][4];
#pragma unroll
        for (int ch = 0; ch < 4; ch++) {
            float4 bv = *(const float4*)&sbx[ch * 64 + hg * 4];
            acc[ch][0] = make_float4(bv.x, bv.x, bv.x, bv.x);
            acc[ch][1] = make_float4(bv.y, bv.y, bv.y, bv.y);
            acc[ch][2] = make_float4(bv.z, bv.z, bv.z, bv.z);
            acc[ch][3] = make_float4(bv.w, bv.w, bv.w, bv.w);
        }
#pragma unroll
        for (int j = 0; j < 4; j++) {
            float4 xv = *(const float4*)&inp_sm[j * 64 + rg * 4];
#pragma unroll
            for (int ch = 0; ch < 4; ch++) {
                float4 wv = *(const float4*)&sWx[j * 256 + ch * 64 + hg * 4];
                fma4(acc[ch][0], xv, wv.x);
                fma4(acc[ch][1], xv, wv.y);
                fma4(acc[ch][2], xv, wv.z);
                fma4(acc[ch][3], xv, wv.w);
            }
        }
#pragma unroll 4
        for (int k = 0; k < 64; k++) {
            float4 hv = *(const float4*)&h_sm[k * 64 + rg * 4];
#pragma unroll
            for (int ch = 0; ch < 4; ch++) {
                float4 wv = *(const float4*)&sWt[k * 256 + ch * 64 + hg * 4];
                fma4(acc[ch][0], hv, wv.x);
                fma4(acc[ch][1], hv, wv.y);
                fma4(acc[ch][2], hv, wv.z);
                fma4(acc[ch][3], hv, wv.w);
            }
        }
        __syncthreads();
#pragma unroll
        for (int hi = 0; hi < 4; hi++) {
            float4 iv = acc[0][hi], fv = acc[1][hi], gv = acc[2][hi], ov = acc[3][hi];
            float4 c = creg[hi];
            float4 hn;
            c.x = sigf(fv.x) * c.x + sigf(iv.x) * tanhf(gv.x); hn.x = sigf(ov.x) * tanhf(c.x);
            c.y = sigf(fv.y) * c.y + sigf(iv.y) * tanhf(gv.y); hn.y = sigf(ov.y) * tanhf(c.y);
            c.z = sigf(fv.z) * c.z + sigf(iv.z) * tanhf(gv.z); hn.z = sigf(ov.z) * tanhf(c.z);
            c.w = sigf(fv.w) * c.w + sigf(iv.w) * tanhf(gv.w); hn.w = sigf(ov.w) * tanhf(c.w);
            creg[hi] = c;
            *(float4*)&h_sm[(hg * 4 + hi) * 64 + rg * 4] = hn;
        }
        __syncthreads();  // new h visible to control readers
        if (tid < 64) {
            float p = sbc[0], s = sbc[1];
            for (int k = 0; k < 64; k++) {
                float h = h_sm[k * 64 + tid];
                p = fmaf(h, sWc[k], p);
                s = fmaf(h, sWc[64 + k], s);
            }
            float steer = fminf(fmaxf(s, -0.5f), 0.5f);
            float v1 = fminf(fmaxf(prev.w + p * 0.03f, 0.0f), 30.0f);
            float psidot = fminf(fmaxf(prev.w * tanf(steer) / 2.5f, -1.57f), 1.57f);
            float4 cur;
            cur.x = prev.x + prev.w * cosf(prev.z) * 0.03f;
            cur.y = prev.y + prev.w * sinf(prev.z) * 0.03f;
            cur.z = prev.z + psidot * 0.03f;
            cur.w = v1;
            *(float4*)&recons[(size_t)(base + tid) * 120 + t * 4] = cur;
            prev = cur;
        }
    }
}

// ---------------- launch ----------------
extern "C" void kernel_launch(void* const* d_in, const int* in_sizes, int n_in,
                              void* d_out, int out_size) {
    const float* traj = (const float*)d_in[0];
    const float* inits = (const float*)d_in[1];
    const float* eps = (const float*)d_in[2];
    const float* W_se = (const float*)d_in[3];
    const float* b_se = (const float*)d_in[4];
    const float* W_ih_e = (const float*)d_in[5];
    const float* W_hh_e = (const float*)d_in[6];
    const float* b_ih_e = (const float*)d_in[7];
    const float* b_hh_e = (const float*)d_in[8];
    const float* mean_Ws = (const float*)d_in[9];
    const float* mean_bs = (const float*)d_in[10];
    const float* mean_Wf = (const float*)d_in[11];
    const float* mean_bf = (const float*)d_in[12];
    const float* lv_Ws = (const float*)d_in[13];
    const float* lv_bs = (const float*)d_in[14];
    const float* lv_Wf = (const float*)d_in[15];
    const float* lv_bf = (const float*)d_in[16];
    const float* W_init = (const float*)d_in[17];
    const float* b_init = (const float*)d_in[18];
    const float* W_ih_d = (const float*)d_in[19];
    const float* W_hh_d = (const float*)d_in[20];
    const float* b_ih_d = (const float*)d_in[21];
    const float* b_hh_d = (const float*)d_in[22];
    const float* W_c = (const float*)d_in[23];
    const float* b_c = (const float*)d_in[24];
    float* out = (float*)d_out;
    const int B = in_sizes[0] / 120;

    const int SMEM_ENC = 22016 * 4;
    const int SMEM_DEC = 22148 * 4;
    const int SMEM_MLP = 31616 * 4;
    cudaFuncSetAttribute(k_enc, cudaFuncAttributeMaxDynamicSharedMemorySize, SMEM_ENC);
    cudaFuncSetAttribute(k_dec, cudaFuncAttributeMaxDynamicSharedMemorySize, SMEM_DEC);
    cudaFuncSetAttribute(k_mlp, cudaFuncAttributeMaxDynamicSharedMemorySize, SMEM_MLP);

    k_fold<<<1, 256>>>(W_se, b_se, W_ih_e, W_hh_e, b_ih_e, b_hh_e,
                       W_ih_d, W_hh_d, b_ih_d, b_hh_d);
    int nEps = 100 * B;
    k_epsT<<<(nEps + 255) / 256, 256>>>(eps, B);
    int n4 = (B * 120) / 4;
    k_copy<<<(n4 + 255) / 256, 256>>>((const float4*)traj, (float4*)(out + (size_t)B * 120), n4);
    k_enc<<<B / 64, 256, SMEM_ENC>>>(traj, B);
    k_mlp<<<B / 64, 256, SMEM_MLP>>>(mean_Ws, mean_bs, mean_Wf, mean_bf,
                                     lv_Ws, lv_bs, lv_Wf, lv_bf, W_init, b_init,
                                     out + (size_t)B * 240, out + (size_t)B * 340, B);
    k_dec<<<B / 64, 256, SMEM_DEC>>>(inits, W_c, b_c, out, B);
}